// round 15
// baseline (speedup 1.0000x reference)
#include <cuda_runtime.h>
#include <math.h>

#define BB 32
#define AA 8732
#define CC 201
#define GG 50
#define TPB 256
#define APW 8                  // anchors per warp
#define APB 64                 // anchors per block (8 warps)
#define BPR 137                // ceil(8732/64)
#define MAXFG 1024
#define NBIN 1024
#define QS 64.0f               // bin width 1/64
#define FPS 4096.0f            // fixed-point sum scale
#define SUMMASK ((1ull << 40) - 1)
#define BPT (NBIN / TPB)       // 4 bins per thread in select phase

// Scratch (no allocations). All state self-resets for graph replay.
__device__ unsigned long long g_hist[BB * NBIN];  // packed {count<<40 | fpsum}
__device__ float2   g_fg[BB * MAXFG];
__device__ int      g_row_nfg[BB];
__device__ int      g_row_done[BB];
__device__ float4   g_row_out[BB];
__device__ int      g_done;

__device__ __forceinline__ int atom_add_release(int* p, int v) {
    int old;
    asm volatile("atom.release.gpu.global.add.s32 %0, [%1], %2;"
                 : "=r"(old) : "l"(p), "r"(v) : "memory");
    return old;
}

__global__ void __launch_bounds__(TPB)
fused_kernel(const float* __restrict__ boxes,
             const int*   __restrict__ labels,
             const int*   __restrict__ img_label,
             const float* __restrict__ bbox_reg,
             const float* __restrict__ cls_logits,
             const float* __restrict__ rej,
             const float* __restrict__ anchors,
             const int*   __restrict__ matched,
             float*       __restrict__ out) {
    __shared__ int   swc[8];
    __shared__ float swf[8];
    __shared__ float sf1[8], sf2[8];
    __shared__ int   sB, sCex;
    __shared__ float sFex;
    __shared__ int   sflag, gflag;

    int b    = blockIdx.y;
    int tid  = threadIdx.x;
    int wid  = tid >> 5;
    int lane = tid & 31;
    int a0   = blockIdx.x * APB + wid * APW;    // row-local anchor base

    // ================= streaming phase: 8 anchors per warp =================
    if (a0 < AA) {
        const float* lp = cls_logits + ((size_t)b * AA + a0) * CC;

        float v[APW][7];
#pragma unroll
        for (int i = 0; i < APW; i++) {
            bool va = (a0 + i) < AA;
#pragma unroll
            for (int j = 0; j < 7; j++) {
                int c = lane + 32 * j;
                v[i][j] = (va && c < CC) ? __ldcs(lp + i * CC + c) : 0.f;
            }
        }

        float s[APW];
#pragma unroll
        for (int i = 0; i < APW; i++) s[i] = 0.f;
#pragma unroll
        for (int j = 0; j < 6; j++)
#pragma unroll
            for (int i = 0; i < APW; i++) s[i] += __expf(v[i][j]);
        if (lane < 9)
#pragma unroll
            for (int i = 0; i < APW; i++) s[i] += __expf(v[i][6]);
#pragma unroll
        for (int o = 16; o; o >>= 1)
#pragma unroll
            for (int i = 0; i < APW; i++)
                s[i] += __shfl_xor_sync(0xffffffffu, s[i], o);

        if (lane < APW && (a0 + lane) < AA) {
            float ss = s[0];
#pragma unroll
            for (int i = 1; i < APW; i++) if (lane == i) ss = s[i];
            int  gw = b * AA + a0 + lane;
            int  m  = matched[gw];
            bool fg = (m >= 0);
            int  t  = fg ? labels[b * GG + m] : 0;
            float cls = __logf(ss) - cls_logits[(size_t)gw * CC + t];
            if (!fg) {
                float cc = fmaxf(cls, 0.f);
                int   q  = min((int)(cc * QS), NBIN - 1);
                unsigned long long pk =
                    (1ull << 40) | (unsigned long long)(unsigned)(cc * FPS);
                atomicAdd(&g_hist[b * NBIN + q], pk);
            } else {
                const float* anc = anchors + (size_t)gw * 4;
                const float* gt  = boxes + ((size_t)b * GG + m) * 4;
                float a_ = anc[0], b_ = anc[1], c_ = anc[2], d_ = anc[3];
                float g0 = gt[0],  g1 = gt[1],  g2 = gt[2],  g3 = gt[3];
                float awd = c_ - a_, aht = d_ - b_;
                float acx = a_ + 0.5f * awd, acy = b_ + 0.5f * aht;
                float gwd = g2 - g0, ght = g3 - g1;
                float gcx = g0 + 0.5f * gwd, gcy = g1 + 0.5f * ght;
                float tt0 = 10.f * (gcx - acx) / awd;
                float tt1 = 10.f * (gcy - acy) / aht;
                float tt2 = 5.f * logf(gwd / awd);
                float tt3 = 5.f * logf(ght / aht);
                const float* r = bbox_reg + (size_t)gw * 4;
                float d0 = r[0] - tt0, d1 = r[1] - tt1;
                float d2 = r[2] - tt2, d3 = r[3] - tt3;
                float q0 = fabsf(d0), q1 = fabsf(d1);
                float q2 = fabsf(d2), q3 = fabsf(d3);
                float bbx;
                bbx  = (q0 < 1.f) ? 0.5f * d0 * d0 : (q0 - 0.5f);
                bbx += (q1 < 1.f) ? 0.5f * d1 * d1 : (q1 - 0.5f);
                bbx += (q2 < 1.f) ? 0.5f * d2 * d2 : (q2 - 0.5f);
                bbx += (q3 < 1.f) ? 0.5f * d3 * d3 : (q3 - 0.5f);
                int slot = atomicAdd(&g_row_nfg[b], 1);
                g_fg[b * MAXFG + slot] = make_float2(cls, bbx);
            }
        }
    }

    // Release-ordered row-done count (no per-block threadfence).
    __syncthreads();
    if (tid == 0)
        sflag = (atom_add_release(&g_row_done[b], 1) == BPR - 1);
    __syncthreads();
    if (!sflag) return;

    // ============ row-last block: histogram top-k (R14-proven) ============
    __threadfence();   // acquire; 32 blocks total ever reach here

    ulonglong2* hp = (ulonglong2*)(g_hist + b * NBIN);
    int   h[BPT];
    float f[BPT];
#pragma unroll
    for (int j = 0; j < BPT / 2; j++) {
        ulonglong2 pv = __ldcg(&hp[tid * (BPT / 2) + j]);
        h[2 * j + 0] = (int)(pv.x >> 40);
        h[2 * j + 1] = (int)(pv.y >> 40);
        f[2 * j + 0] = (float)(pv.x & SUMMASK) * (1.0f / FPS);
        f[2 * j + 1] = (float)(pv.y & SUMMASK) * (1.0f / FPS);
    }

    int nfg = __ldcg(&g_row_nfg[b]);
    float fgc = 0.f, bbs = 0.f;
    for (int i = tid; i < nfg; i += TPB) {
        float2 d = __ldcg(&g_fg[b * MAXFG + i]);
        fgc += d.x;
        bbs += d.y;
    }
#pragma unroll
    for (int o = 16; o; o >>= 1) {
        fgc += __shfl_xor_sync(0xffffffffu, fgc, o);
        bbs += __shfl_xor_sync(0xffffffffu, bbs, o);
    }
    if (lane == 0) { sf1[wid] = fgc; sf2[wid] = bbs; }

    int   tc = 0;
    float tf = 0.f;
#pragma unroll
    for (int j = 0; j < BPT; j++) { tc += h[j]; tf += f[j]; }
    int   sc  = tc;
    float sfx = tf;
#pragma unroll
    for (int o = 1; o < 32; o <<= 1) {
        int   t = __shfl_down_sync(0xffffffffu, sc, o);
        float g = __shfl_down_sync(0xffffffffu, sfx, o);
        if (lane + o < 32) { sc += t; sfx += g; }
    }
    if (lane == 0) { swc[wid] = sc; swf[wid] = sfx; }
    if (tid == 0) sB = -1;
    __syncthreads();

    float row_fgc = 0.f, row_bbx = 0.f;
#pragma unroll
    for (int w = 0; w < 8; w++) { row_fgc += sf1[w]; row_bbx += sf2[w]; }

    int k = 3 * nfg;
    float bg = 0.f;
    if (k > 0) {
        int   aw = 0;
        float awf = 0.f;
#pragma unroll
        for (int w = 0; w < 8; w++)
            if (w > wid) { aw += swc[w]; awf += swf[w]; }
        int   cab = aw + (sc - tc);
        float fab = awf + (sfx - tf);

        if (cab < k && cab + tc >= k) {
            int   run = cab;
            float fr  = fab;
#pragma unroll
            for (int j = BPT - 1; j >= 0; --j) {
                int nr = run + h[j];
                if (nr >= k) { sB = tid * BPT + j; sCex = run; sFex = fr; break; }
                run = nr;
                fr += f[j];
            }
        }
        __syncthreads();
        bg = sFex + (float)(k - sCex) * ((float)sB * (1.0f / QS));
    } else {
        __syncthreads();
    }

    // Reset row state for next graph replay.
    ulonglong2 z2 = make_ulonglong2(0ull, 0ull);
#pragma unroll
    for (int j = 0; j < BPT / 2; j++) hp[tid * (BPT / 2) + j] = z2;

    if (tid == 0) {
        g_row_out[b] = make_float4(row_fgc, bg, row_bbx, (float)nfg);
        g_row_nfg[b]  = 0;
        g_row_done[b] = 0;
        gflag = (atom_add_release(&g_done, 1) == BB - 1);
    }
    __syncthreads();
    if (!gflag) return;

    // ================= global-last block: finalize =================
    if (tid < 32) {
        __threadfence();
        float4 r = __ldcg(&g_row_out[tid]);
        float l0 = rej[2 * tid], l1 = rej[2 * tid + 1];
        float mm = fmaxf(l0, l1);
        float lse = mm + __logf(__expf(l0 - mm) + __expf(l1 - mm));
        float vl = lse - (img_label[tid] == 0 ? l0 : l1);
        float fc = r.x, bgs = r.y, bx = r.z, cn = r.w;
#pragma unroll
        for (int o = 16; o; o >>= 1) {
            fc  += __shfl_xor_sync(0xffffffffu, fc,  o);
            bgs += __shfl_xor_sync(0xffffffffu, bgs, o);
            bx  += __shfl_xor_sync(0xffffffffu, bx,  o);
            cn  += __shfl_xor_sync(0xffffffffu, cn,  o);
            vl  += __shfl_xor_sync(0xffffffffu, vl,  o);
        }
        if (tid == 0) {
            float N   = fmaxf(1.f, cn);
            float reg = bx / N;
            float cls = (fc + bgs) / N;
            float v   = vl / (float)BB;
            out[0] = 0.5f * (reg + cls) + 0.5f * v;
            out[1] = reg;
            out[2] = cls;
            out[3] = v;
            g_done = 0;
        }
    }
}

extern "C" void kernel_launch(void* const* d_in, const int* in_sizes, int n_in,
                              void* d_out, int out_size) {
    const float* boxes      = (const float*)d_in[0];
    const int*   labels     = (const int*)  d_in[1];
    const int*   image_lab  = (const int*)  d_in[2];
    const float* bbox_reg   = (const float*)d_in[3];
    const float* cls_logits = (const float*)d_in[4];
    const float* rej        = (const float*)d_in[5];
    const float* anchors    = (const float*)d_in[6];
    const int*   matched    = (const int*)  d_in[7];

    dim3 grid(BPR, BB);
    fused_kernel<<<grid, TPB>>>(boxes, labels, image_lab, bbox_reg, cls_logits,
                                rej, anchors, matched, (float*)d_out);
}

// round 16
// speedup vs baseline: 1.3919x; 1.3919x over previous
#include <cuda_runtime.h>
#include <math.h>

#define BB 32
#define AA 8732
#define CC 201
#define GG 50
#define TPB 256
#define APW 8                 // anchors per warp
#define MAXFG 1024
#define NBIN 1024
#define QS 64.0f              // bin width 1/64
#define FPS 4096.0f           // fixed-point sum scale
#define SUMMASK ((1ull << 40) - 1)
#define GRPF (APW * CC)       // 1608 floats per warp group
#define NIT 13                // ceil(1608 / 128)

// Scratch (no allocations). All state self-resets for graph replay.
__device__ unsigned long long g_hist[BB * NBIN];  // packed {count<<40 | fpsum}
__device__ float2   g_fg[BB * MAXFG];
__device__ int      g_row_nfg[BB];
__device__ float4   g_row_out[BB];
__device__ int      g_done;

// ---------------------------------------------------------------------------
// Kernel 1: EIGHT anchors per warp via 13 x LDG.128 per lane (vs 56 scalar
// LDGs). 128-elem windows span <=2 anchors with compile-time split; exps
// accumulate into 8 buckets, one 5-step butterfly reduces all 8.
// ---------------------------------------------------------------------------
__global__ void __launch_bounds__(TPB)
main_kernel(const float* __restrict__ boxes,
            const int*   __restrict__ labels,
            const float* __restrict__ bbox_reg,
            const float* __restrict__ cls_logits,
            const float* __restrict__ anchors,
            const int*   __restrict__ matched) {
    int tid  = threadIdx.x;
    int wid  = tid >> 5;
    int lane = tid & 31;
    int base = (blockIdx.x * (TPB / 32) + wid) * APW;     // first anchor of group
    const float4* lp4 = (const float4*)(cls_logits + (size_t)base * CC);  // 16B-aligned

    // Batched vector loads (MLP = 13 x LDG.128).
    float4 d[NIT];
#pragma unroll
    for (int it = 0; it < NIT; it++) {
        int e = it * 128 + lane * 4;
        if (e < GRPF)
            d[it] = __ldcs(lp4 + it * 32 + lane);
        else
            d[it] = make_float4(-1e30f, -1e30f, -1e30f, -1e30f);  // exp -> 0
    }

    // Exp + bucket accumulation; anchor split per window is compile-time.
    float acc[APW];
#pragma unroll
    for (int i = 0; i < APW; i++) acc[i] = 0.f;
#pragma unroll
    for (int it = 0; it < NIT; it++) {
        const int A0  = (it * 128) / CC;        // first anchor in window
        const int BND = (A0 + 1) * CC;          // its end element
        const bool SPLIT = (BND < it * 128 + 128) && (A0 + 1 < APW);
        float ex0 = __expf(d[it].x);
        float ex1 = __expf(d[it].y);
        float ex2 = __expf(d[it].z);
        float ex3 = __expf(d[it].w);
        int e = it * 128 + lane * 4;
        if (SPLIT) {
            acc[A0]                       += (e + 0 < BND) ? ex0 : 0.f;
            acc[(A0 + 1) & (APW - 1)]     += (e + 0 < BND) ? 0.f : ex0;
            acc[A0]                       += (e + 1 < BND) ? ex1 : 0.f;
            acc[(A0 + 1) & (APW - 1)]     += (e + 1 < BND) ? 0.f : ex1;
            acc[A0]                       += (e + 2 < BND) ? ex2 : 0.f;
            acc[(A0 + 1) & (APW - 1)]     += (e + 2 < BND) ? 0.f : ex2;
            acc[A0]                       += (e + 3 < BND) ? ex3 : 0.f;
            acc[(A0 + 1) & (APW - 1)]     += (e + 3 < BND) ? 0.f : ex3;
        } else {
            acc[A0] += ex0 + ex1 + ex2 + ex3;   // padded lanes add exp(-1e30)=0
        }
    }

    // One butterfly reduces all 8 buckets; every lane ends with all totals.
#pragma unroll
    for (int o = 16; o; o >>= 1)
#pragma unroll
        for (int i = 0; i < APW; i++)
            acc[i] += __shfl_xor_sync(0xffffffffu, acc[i], o);

    if (lane < APW) {
        float ss = acc[0];
#pragma unroll
        for (int i = 1; i < APW; i++) if (lane == i) ss = acc[i];
        int  gw = base + lane;
        int  b  = gw / AA;
        int  m  = matched[gw];
        bool fg = (m >= 0);
        int  t  = fg ? labels[b * GG + m] : 0;
        float cls = __logf(ss) - cls_logits[(size_t)gw * CC + t];
        if (!fg) {
            float cc = fmaxf(cls, 0.f);
            int   q  = min((int)(cc * QS), NBIN - 1);
            unsigned long long pk =
                (1ull << 40) | (unsigned long long)(unsigned)(cc * FPS);
            atomicAdd(&g_hist[b * NBIN + q], pk);
        } else {
            const float* anc = anchors + (size_t)gw * 4;
            const float* gt  = boxes + ((size_t)b * GG + m) * 4;
            float a0 = anc[0], a1 = anc[1], a2 = anc[2], a3 = anc[3];
            float g0 = gt[0],  g1 = gt[1],  g2 = gt[2],  g3 = gt[3];
            float awd = a2 - a0, aht = a3 - a1;
            float acx = a0 + 0.5f * awd, acy = a1 + 0.5f * aht;
            float gwd = g2 - g0, ght = g3 - g1;
            float gcx = g0 + 0.5f * gwd, gcy = g1 + 0.5f * ght;
            float tt0 = 10.f * (gcx - acx) / awd;
            float tt1 = 10.f * (gcy - acy) / aht;
            float tt2 = 5.f * logf(gwd / awd);
            float tt3 = 5.f * logf(ght / aht);
            const float* r = bbox_reg + (size_t)gw * 4;
            float d0 = r[0] - tt0, d1 = r[1] - tt1;
            float d2 = r[2] - tt2, d3 = r[3] - tt3;
            float q0 = fabsf(d0), q1 = fabsf(d1);
            float q2 = fabsf(d2), q3 = fabsf(d3);
            float bbx;
            bbx  = (q0 < 1.f) ? 0.5f * d0 * d0 : (q0 - 0.5f);
            bbx += (q1 < 1.f) ? 0.5f * d1 * d1 : (q1 - 0.5f);
            bbx += (q2 < 1.f) ? 0.5f * d2 * d2 : (q2 - 0.5f);
            bbx += (q3 < 1.f) ? 0.5f * d3 * d3 : (q3 - 0.5f);
            int slot = atomicAdd(&g_row_nfg[b], 1);
            g_fg[b * MAXFG + slot] = make_float2(cls, bbx);
        }
    }
}

// ---------------------------------------------------------------------------
// Kernel 2 (R14-proven): per-row top-k from packed histogram, one suffix-scan.
// ---------------------------------------------------------------------------
#define ST 256
#define BPT (NBIN / ST)       // 4 bins per thread

__global__ void __launch_bounds__(ST)
select_kernel(const float* __restrict__ rej,
              const int*   __restrict__ img_label,
              float*       __restrict__ out) {
    __shared__ int   swc[8];
    __shared__ float swf[8];
    __shared__ float sf1[8], sf2[8];
    __shared__ int   sB, sCex;
    __shared__ float sFex;
    __shared__ int   is_last;

    int b    = blockIdx.x;
    int tid  = threadIdx.x;
    int lane = tid & 31;
    int wid  = tid >> 5;

    ulonglong2* hp = (ulonglong2*)(g_hist + b * NBIN);
    int   h[BPT];
    float f[BPT];
#pragma unroll
    for (int j = 0; j < BPT / 2; j++) {
        ulonglong2 pv = hp[tid * (BPT / 2) + j];
        h[2 * j + 0] = (int)(pv.x >> 40);
        h[2 * j + 1] = (int)(pv.y >> 40);
        f[2 * j + 0] = (float)(pv.x & SUMMASK) * (1.0f / FPS);
        f[2 * j + 1] = (float)(pv.y & SUMMASK) * (1.0f / FPS);
    }

    int nfg = g_row_nfg[b];
    float fgc = 0.f, bbx = 0.f;
    for (int i = tid; i < nfg; i += ST) {
        float2 d = g_fg[b * MAXFG + i];
        fgc += d.x;
        bbx += d.y;
    }
#pragma unroll
    for (int o = 16; o; o >>= 1) {
        fgc += __shfl_xor_sync(0xffffffffu, fgc, o);
        bbx += __shfl_xor_sync(0xffffffffu, bbx, o);
    }
    if (lane == 0) { sf1[wid] = fgc; sf2[wid] = bbx; }

    int   tc = 0;
    float tf = 0.f;
#pragma unroll
    for (int j = 0; j < BPT; j++) { tc += h[j]; tf += f[j]; }
    int   sc  = tc;
    float sfx = tf;
#pragma unroll
    for (int o = 1; o < 32; o <<= 1) {
        int   t = __shfl_down_sync(0xffffffffu, sc, o);
        float g = __shfl_down_sync(0xffffffffu, sfx, o);
        if (lane + o < 32) { sc += t; sfx += g; }
    }
    if (lane == 0) { swc[wid] = sc; swf[wid] = sfx; }
    if (tid == 0) sB = -1;
    __syncthreads();

    float row_fgc = 0.f, row_bbx = 0.f;
#pragma unroll
    for (int w = 0; w < 8; w++) { row_fgc += sf1[w]; row_bbx += sf2[w]; }

    int k = 3 * nfg;
    float bg = 0.f;
    if (k > 0) {
        int   aw = 0;
        float awf = 0.f;
#pragma unroll
        for (int w = 0; w < 8; w++)
            if (w > wid) { aw += swc[w]; awf += swf[w]; }
        int   cab = aw + (sc - tc);
        float fab = awf + (sfx - tf);

        if (cab < k && cab + tc >= k) {
            int   run = cab;
            float fr  = fab;
#pragma unroll
            for (int j = BPT - 1; j >= 0; --j) {
                int nr = run + h[j];
                if (nr >= k) { sB = tid * BPT + j; sCex = run; sFex = fr; break; }
                run = nr;
                fr += f[j];
            }
        }
        __syncthreads();
        bg = sFex + (float)(k - sCex) * ((float)sB * (1.0f / QS));
    } else {
        __syncthreads();
    }

    ulonglong2 z2 = make_ulonglong2(0ull, 0ull);
#pragma unroll
    for (int j = 0; j < BPT / 2; j++) hp[tid * (BPT / 2) + j] = z2;

    if (tid == 0) {
        g_row_out[b] = make_float4(row_fgc, bg, row_bbx, (float)nfg);
        g_row_nfg[b] = 0;
        __threadfence();
        is_last = (atomicAdd(&g_done, 1) == BB - 1);
    }
    __syncthreads();

    if (is_last && tid < 32) {
        __threadfence();
        float4 r = __ldcg(&g_row_out[tid]);
        float l0 = rej[2 * tid], l1 = rej[2 * tid + 1];
        float mm = fmaxf(l0, l1);
        float lse = mm + __logf(__expf(l0 - mm) + __expf(l1 - mm));
        float vl = lse - (img_label[tid] == 0 ? l0 : l1);
        float fc = r.x, bgs = r.y, bx = r.z, cn = r.w;
#pragma unroll
        for (int o = 16; o; o >>= 1) {
            fc  += __shfl_xor_sync(0xffffffffu, fc,  o);
            bgs += __shfl_xor_sync(0xffffffffu, bgs, o);
            bx  += __shfl_xor_sync(0xffffffffu, bx,  o);
            cn  += __shfl_xor_sync(0xffffffffu, cn,  o);
            vl  += __shfl_xor_sync(0xffffffffu, vl,  o);
        }
        if (tid == 0) {
            float N   = fmaxf(1.f, cn);
            float reg = bx / N;
            float cls = (fc + bgs) / N;
            float v   = vl / (float)BB;
            out[0] = 0.5f * (reg + cls) + 0.5f * v;
            out[1] = reg;
            out[2] = cls;
            out[3] = v;
            g_done = 0;
        }
    }
}

extern "C" void kernel_launch(void* const* d_in, const int* in_sizes, int n_in,
                              void* d_out, int out_size) {
    const float* boxes      = (const float*)d_in[0];
    const int*   labels     = (const int*)  d_in[1];
    const int*   image_lab  = (const int*)  d_in[2];
    const float* bbox_reg   = (const float*)d_in[3];
    const float* cls_logits = (const float*)d_in[4];
    const float* rej        = (const float*)d_in[5];
    const float* anchors    = (const float*)d_in[6];
    const int*   matched    = (const int*)  d_in[7];

    const int blocks = (BB * AA) / (APW * (TPB / 32));   // 4366 exact
    main_kernel<<<blocks, TPB>>>(boxes, labels, bbox_reg, cls_logits,
                                 anchors, matched);

    select_kernel<<<BB, ST>>>(rej, image_lab, (float*)d_out);
}